// round 6
// baseline (speedup 1.0000x reference)
#include <cuda_runtime.h>
#include <math.h>

#define BATCH 4
#define SEQ   1024
#define DIM   1024
#define NH    16
#define DH    64
#define PAD   65

// Scratch (allocation-free): qkv = [B*T, 3*DIM], att = [B*T, DIM]
__device__ float g_qkv[BATCH * SEQ * 3 * DIM];
__device__ float g_att[BATCH * SEQ * DIM];

// ---------------------------------------------------------------------------
// SGEMM: C[M,N] = A[M,K] @ B[K,N], row-major, 128x128 tile, 8x8 per thread.
// ---------------------------------------------------------------------------
__global__ __launch_bounds__(256) void sgemm128(const float* __restrict__ A,
                                                const float* __restrict__ B,
                                                float* __restrict__ C,
                                                int M, int N, int K) {
    __shared__ float As[8][128];
    __shared__ float Bs[8][128];

    const int tid  = threadIdx.x;
    const int row0 = blockIdx.y * 128;
    const int col0 = blockIdx.x * 128;

    const int a_row = tid >> 1;
    const int a_col = (tid & 1) << 2;
    const int b_row = tid >> 5;
    const int b_col = (tid & 31) << 2;

    const int ty = tid >> 4;
    const int tx = tid & 15;

    float acc[8][8];
#pragma unroll
    for (int i = 0; i < 8; i++)
#pragma unroll
        for (int j = 0; j < 8; j++) acc[i][j] = 0.0f;

    const float* Ap = A + (size_t)(row0 + a_row) * K + a_col;
    const float* Bp = B + (size_t)b_row * N + col0 + b_col;

    for (int k0 = 0; k0 < K; k0 += 8) {
        float4 a4 = *(const float4*)(Ap + k0);
        As[a_col + 0][a_row] = a4.x;
        As[a_col + 1][a_row] = a4.y;
        As[a_col + 2][a_row] = a4.z;
        As[a_col + 3][a_row] = a4.w;
        *(float4*)&Bs[b_row][b_col] = *(const float4*)(Bp + (size_t)k0 * N);
        __syncthreads();

#pragma unroll
        for (int k = 0; k < 8; k++) {
            float aa[8], bb[8];
#pragma unroll
            for (int i = 0; i < 4; i++) aa[i]     = As[k][(ty << 2) + i];
#pragma unroll
            for (int i = 0; i < 4; i++) aa[4 + i] = As[k][64 + (ty << 2) + i];
#pragma unroll
            for (int j = 0; j < 4; j++) bb[j]     = Bs[k][(tx << 2) + j];
#pragma unroll
            for (int j = 0; j < 4; j++) bb[4 + j] = Bs[k][64 + (tx << 2) + j];
#pragma unroll
            for (int i = 0; i < 8; i++)
#pragma unroll
                for (int j = 0; j < 8; j++)
                    acc[i][j] = fmaf(aa[i], bb[j], acc[i][j]);
        }
        __syncthreads();
    }

#pragma unroll
    for (int i = 0; i < 8; i++) {
        int r = row0 + ((i < 4) ? (ty * 4 + i) : (64 + ty * 4 + i - 4));
        float4 c0 = make_float4(acc[i][0], acc[i][1], acc[i][2], acc[i][3]);
        float4 c1 = make_float4(acc[i][4], acc[i][5], acc[i][6], acc[i][7]);
        *(float4*)&C[(size_t)r * N + col0 + (tx << 2)]      = c0;
        *(float4*)&C[(size_t)r * N + col0 + 64 + (tx << 2)] = c1;
    }
}

// ---------------------------------------------------------------------------
// RoPE — interleaved pairs (2i, 2i+1), freqs repeated, **sin sign FLIPPED**
// (rotation by -theta):
//   out[2i]   = t[2i]  *cos + t[2i+1]*sin
//   out[2i+1] = t[2i+1]*cos - t[2i]  *sin
// f_i = pos * 10000^(-2i/32)
// idx bits: [0:4)=i, [4:8)=head, [8]=s (0=q,1=k), [9:19)=t, [19:21)=b
// ---------------------------------------------------------------------------
__global__ void rope_kernel(float* __restrict__ qkv) {
    int idx = blockIdx.x * blockDim.x + threadIdx.x;
    int i = idx & 15;
    int h = (idx >> 4) & 15;
    int s = (idx >> 8) & 1;
    int t = (idx >> 9) & 1023;
    int b = idx >> 19;

    float inv_freq = powf(10000.0f, -(float)(2 * i) / 32.0f);
    float ang = (float)t * inv_freq;
    float c, sn;
    sincosf(ang, &c, &sn);

    size_t base = ((size_t)(b * SEQ + t)) * (3 * DIM) + s * DIM + h * DH + 2 * i;
    float v0 = qkv[base], v1 = qkv[base + 1];
    qkv[base]     = v0 * c + v1 * sn;   // sign flipped vs rounds 1-4
    qkv[base + 1] = v1 * c - v0 * sn;
}

// ---------------------------------------------------------------------------
// Flash attention (causal), fp32. One block per (q-tile=64, head, batch).
// ---------------------------------------------------------------------------
__global__ __launch_bounds__(256) void attn_kernel(const float* __restrict__ qkv,
                                                   float* __restrict__ out) {
    extern __shared__ float sm[];
    float* Qs = sm;
    float* Kt = Qs + 64 * PAD;
    float* Vs = Kt + 64 * PAD;
    float* Ps = Vs + 64 * PAD;

    const int qt = blockIdx.x;
    const int h  = blockIdx.y;
    const int b  = blockIdx.z;
    const int tid = threadIdx.x;
    const int ty = tid >> 4, tx = tid & 15;
    const int lr = tid >> 4, lc4 = (tid & 15) << 2;

    const float* qb = qkv + ((size_t)(b * SEQ + qt * 64)) * (3 * DIM) + h * DH;
#pragma unroll
    for (int rr = 0; rr < 4; rr++) {
        int row = rr * 16 + lr;
        float4 v = *(const float4*)(qb + (size_t)row * (3 * DIM) + lc4);
        Qs[row * PAD + lc4 + 0] = v.x;
        Qs[row * PAD + lc4 + 1] = v.y;
        Qs[row * PAD + lc4 + 2] = v.z;
        Qs[row * PAD + lc4 + 3] = v.w;
    }

    float m_[4], l_[4], acc[4][4];
#pragma unroll
    for (int i = 0; i < 4; i++) {
        m_[i] = -INFINITY;
        l_[i] = 0.0f;
#pragma unroll
        for (int j = 0; j < 4; j++) acc[i][j] = 0.0f;
    }

    const float scale = 0.125f;

    for (int kt = 0; kt <= qt; kt++) {
        __syncthreads();

        const float* kb = qkv + ((size_t)(b * SEQ + kt * 64)) * (3 * DIM) + DIM + h * DH;
        const float* vb = kb + DIM;
#pragma unroll
        for (int rr = 0; rr < 4; rr++) {
            int row = rr * 16 + lr;
            float4 kv = *(const float4*)(kb + (size_t)row * (3 * DIM) + lc4);
            Kt[(lc4 + 0) * PAD + row] = kv.x;
            Kt[(lc4 + 1) * PAD + row] = kv.y;
            Kt[(lc4 + 2) * PAD + row] = kv.z;
            Kt[(lc4 + 3) * PAD + row] = kv.w;
            float4 vv = *(const float4*)(vb + (size_t)row * (3 * DIM) + lc4);
            Vs[row * PAD + lc4 + 0] = vv.x;
            Vs[row * PAD + lc4 + 1] = vv.y;
            Vs[row * PAD + lc4 + 2] = vv.z;
            Vs[row * PAD + lc4 + 3] = vv.w;
        }
        __syncthreads();

        float s_[4][4] = {{0.f,0.f,0.f,0.f},{0.f,0.f,0.f,0.f},
                          {0.f,0.f,0.f,0.f},{0.f,0.f,0.f,0.f}};
#pragma unroll 8
        for (int d = 0; d < 64; d++) {
            float qv[4], kv[4];
#pragma unroll
            for (int i = 0; i < 4; i++) qv[i] = Qs[(ty * 4 + i) * PAD + d];
#pragma unroll
            for (int j = 0; j < 4; j++) kv[j] = Kt[d * PAD + (tx << 2) + j];
#pragma unroll
            for (int i = 0; i < 4; i++)
#pragma unroll
                for (int j = 0; j < 4; j++) s_[i][j] = fmaf(qv[i], kv[j], s_[i][j]);
        }

#pragma unroll
        for (int i = 0; i < 4; i++) {
            float mx = -INFINITY;
#pragma unroll
            for (int j = 0; j < 4; j++) {
                float sv = s_[i][j] * scale;
                if (kt == qt && ((tx << 2) + j) > (ty * 4 + i)) sv = -INFINITY;
                s_[i][j] = sv;
                mx = fmaxf(mx, sv);
            }
#pragma unroll
            for (int off = 8; off > 0; off >>= 1)
                mx = fmaxf(mx, __shfl_xor_sync(0xffffffffu, mx, off));
            float mn  = fmaxf(m_[i], mx);
            float fac = expf(m_[i] - mn);
            float ps  = 0.0f;
#pragma unroll
            for (int j = 0; j < 4; j++) {
                float p = expf(s_[i][j] - mn);
                s_[i][j] = p;
                ps += p;
            }
#pragma unroll
            for (int off = 8; off > 0; off >>= 1)
                ps += __shfl_xor_sync(0xffffffffu, ps, off);
            m_[i] = mn;
            l_[i] = l_[i] * fac + ps;
#pragma unroll
            for (int j = 0; j < 4; j++) acc[i][j] *= fac;
        }

#pragma unroll
        for (int i = 0; i < 4; i++)
#pragma unroll
            for (int j = 0; j < 4; j++)
                Ps[(ty * 4 + i) * PAD + (tx << 2) + j] = s_[i][j];
        __syncthreads();

#pragma unroll 4
        for (int k = 0; k < 64; k++) {
            float pr[4], vr[4];
#pragma unroll
            for (int i = 0; i < 4; i++) pr[i] = Ps[(ty * 4 + i) * PAD + k];
#pragma unroll
            for (int j = 0; j < 4; j++) vr[j] = Vs[k * PAD + (tx << 2) + j];
#pragma unroll
            for (int i = 0; i < 4; i++)
#pragma unroll
                for (int j = 0; j < 4; j++) acc[i][j] = fmaf(pr[i], vr[j], acc[i][j]);
        }
    }

#pragma unroll
    for (int i = 0; i < 4; i++) {
        float inv = 1.0f / l_[i];
        int grow = b * SEQ + qt * 64 + ty * 4 + i;
        float4 o = make_float4(acc[i][0] * inv, acc[i][1] * inv,
                               acc[i][2] * inv, acc[i][3] * inv);
        *(float4*)&out[(size_t)grow * DIM + h * DH + (tx << 2)] = o;
    }
}

// ---------------------------------------------------------------------------
extern "C" void kernel_launch(void* const* d_in, const int* in_sizes, int n_in,
                              void* d_out, int out_size) {
    const float* x    = nullptr;
    const float* Wqkv = nullptr;
    const float* Wout = nullptr;
    for (int i = 0; i < n_in; i++) {
        if (in_sizes[i] == BATCH * SEQ * DIM)  x    = (const float*)d_in[i];
        else if (in_sizes[i] == 3 * DIM * DIM) Wqkv = (const float*)d_in[i];
        else if (in_sizes[i] == DIM * DIM)     Wout = (const float*)d_in[i];
    }
    float* out = (float*)d_out;

    float* qkv = nullptr;
    float* att = nullptr;
    cudaGetSymbolAddress((void**)&qkv, g_qkv);
    cudaGetSymbolAddress((void**)&att, g_att);

    const int M = BATCH * SEQ;  // 4096

    // 1) QKV projection: [4096,1024] @ [1024,3072]
    sgemm128<<<dim3(3 * DIM / 128, M / 128), 256>>>(x, Wqkv, qkv, M, 3 * DIM, DIM);

    // 2) RoPE (interleaved, -theta) on q and k
    rope_kernel<<<(BATCH * SEQ * 2 * NH * 16) / 256, 256>>>(qkv);

    // 3) Causal flash attention -> att [B,T,DIM]
    int smem = 4 * 64 * PAD * (int)sizeof(float);
    cudaFuncSetAttribute(attn_kernel, cudaFuncAttributeMaxDynamicSharedMemorySize, smem);
    attn_kernel<<<dim3(SEQ / 64, NH, BATCH), 256, smem>>>(qkv, att);

    // 4) Output projection: [4096,1024] @ [1024,1024]
    sgemm128<<<dim3(DIM / 128, M / 128), 256>>>(att, Wout, out, M, DIM, DIM);
}

// round 7
// speedup vs baseline: 1.1184x; 1.1184x over previous
#include <cuda_runtime.h>
#include <math.h>

#define BATCH 4
#define SEQ   1024
#define DIM   1024
#define NH    16
#define DH    64
#define PAD   68   // even, keeps 4-float columns 16B-aligned for pair loads

// packed-f32x2 helpers (sm_103a: one instr = 2 fp32 FMAs)
#define DUP2(d, s)      asm("mov.b64 %0, {%1, %1};" : "=l"(d) : "f"(s))
#define FMA2(a, x, y)   asm("fma.rn.f32x2 %0, %1, %2, %0;" : "+l"(a) : "l"(x), "l"(y))
#define MUL2(a, x)      asm("mul.rn.f32x2 %0, %1, %2;" : "=l"(a) : "l"(a), "l"(x))
#define UNPK2(lo, hi, v) asm("mov.b64 {%0, %1}, %2;" : "=f"(lo), "=f"(hi) : "l"(v))

// Scratch (allocation-free): qkv = [B*T, 3*DIM], att = [B*T, DIM]
__device__ float g_qkv[BATCH * SEQ * 3 * DIM];
__device__ float g_att[BATCH * SEQ * DIM];

// ---------------------------------------------------------------------------
// SGEMM: C[M,N] = A[M,K] @ B[K,N], row-major, 128x128 tile, 8x8 per thread,
// inner product via packed fma.rn.f32x2. (Round-1 version: proven numerically
// identical to the scalar GEMM.)
// ---------------------------------------------------------------------------
__global__ __launch_bounds__(256) void sgemm128(const float* __restrict__ A,
                                                const float* __restrict__ B,
                                                float* __restrict__ C,
                                                int M, int N, int K) {
    __shared__ float As[8][128];   // transposed A tile: As[k][row]
    __shared__ float Bs[8][128];   // Bs[k][col]

    const int tid  = threadIdx.x;
    const int row0 = blockIdx.y * 128;
    const int col0 = blockIdx.x * 128;

    const int a_row = tid >> 1;
    const int a_col = (tid & 1) << 2;
    const int b_row = tid >> 5;
    const int b_col = (tid & 31) << 2;

    const int ty = tid >> 4;
    const int tx = tid & 15;

    unsigned long long acc[8][4];
#pragma unroll
    for (int i = 0; i < 8; i++)
#pragma unroll
        for (int j = 0; j < 4; j++) acc[i][j] = 0ull;

    const float* Ap = A + (size_t)(row0 + a_row) * K + a_col;
    const float* Bp = B + (size_t)b_row * N + col0 + b_col;

    for (int k0 = 0; k0 < K; k0 += 8) {
        float4 a4 = *(const float4*)(Ap + k0);
        As[a_col + 0][a_row] = a4.x;
        As[a_col + 1][a_row] = a4.y;
        As[a_col + 2][a_row] = a4.z;
        As[a_col + 3][a_row] = a4.w;
        *(float4*)&Bs[b_row][b_col] = *(const float4*)(Bp + (size_t)k0 * N);
        __syncthreads();

#pragma unroll
        for (int k = 0; k < 8; k++) {
            float4 a0 = *(const float4*)&As[k][ty << 2];
            float4 a1 = *(const float4*)&As[k][64 + (ty << 2)];
            ulonglong2 b0 = *(const ulonglong2*)&Bs[k][tx << 2];
            ulonglong2 b1 = *(const ulonglong2*)&Bs[k][64 + (tx << 2)];
            float aa[8] = {a0.x, a0.y, a0.z, a0.w, a1.x, a1.y, a1.z, a1.w};
            unsigned long long bb[4] = {b0.x, b0.y, b1.x, b1.y};
#pragma unroll
            for (int i = 0; i < 8; i++) {
                unsigned long long ad;
                DUP2(ad, aa[i]);
#pragma unroll
                for (int j = 0; j < 4; j++) FMA2(acc[i][j], ad, bb[j]);
            }
        }
        __syncthreads();
    }

#pragma unroll
    for (int i = 0; i < 8; i++) {
        int r = row0 + ((i < 4) ? (ty * 4 + i) : (64 + ty * 4 + i - 4));
        ulonglong2 c0 = make_ulonglong2(acc[i][0], acc[i][1]);
        ulonglong2 c1 = make_ulonglong2(acc[i][2], acc[i][3]);
        *(ulonglong2*)&C[(size_t)r * N + col0 + (tx << 2)]      = c0;
        *(ulonglong2*)&C[(size_t)r * N + col0 + 64 + (tx << 2)] = c1;
    }
}

// ---------------------------------------------------------------------------
// RoPE — interleaved pairs (2i, 2i+1), rotation by -theta (verified in R6):
//   out[2i]   = t[2i]  *cos + t[2i+1]*sin
//   out[2i+1] = t[2i+1]*cos - t[2i]  *sin
// ---------------------------------------------------------------------------
__global__ void rope_kernel(float* __restrict__ qkv) {
    int idx = blockIdx.x * blockDim.x + threadIdx.x;
    int i = idx & 15;
    int h = (idx >> 4) & 15;
    int s = (idx >> 8) & 1;
    int t = (idx >> 9) & 1023;
    int b = idx >> 19;

    float inv_freq = powf(10000.0f, -(float)(2 * i) / 32.0f);
    float ang = (float)t * inv_freq;
    float c, sn;
    sincosf(ang, &c, &sn);

    size_t base = ((size_t)(b * SEQ + t)) * (3 * DIM) + s * DIM + h * DH + 2 * i;
    float v0 = qkv[base], v1 = qkv[base + 1];
    qkv[base]     = v0 * c + v1 * sn;
    qkv[base + 1] = v1 * c - v0 * sn;
}

// ---------------------------------------------------------------------------
// Flash attention (causal), fp32, f32x2-packed inner products.
// One block per (q-tile=64, head, batch); 256 threads as 16x16, 4x4/thread.
// ---------------------------------------------------------------------------
__global__ __launch_bounds__(256) void attn_kernel(const float* __restrict__ qkv,
                                                   float* __restrict__ out) {
    extern __shared__ float sm[];
    float* Qs = sm;                  // [64][PAD]
    float* Kt = Qs + 64 * PAD;       // [64][PAD], Kt[d][key]
    float* Vs = Kt + 64 * PAD;       // [64][PAD]
    float* Ps = Vs + 64 * PAD;       // [64][PAD]

    const int qt = blockIdx.x;
    const int h  = blockIdx.y;
    const int b  = blockIdx.z;
    const int tid = threadIdx.x;
    const int ty = tid >> 4, tx = tid & 15;
    const int lr = tid >> 4, lc4 = (tid & 15) << 2;

    const float* qb = qkv + ((size_t)(b * SEQ + qt * 64)) * (3 * DIM) + h * DH;
#pragma unroll
    for (int rr = 0; rr < 4; rr++) {
        int row = rr * 16 + lr;
        float4 v = *(const float4*)(qb + (size_t)row * (3 * DIM) + lc4);
        Qs[row * PAD + lc4 + 0] = v.x;
        Qs[row * PAD + lc4 + 1] = v.y;
        Qs[row * PAD + lc4 + 2] = v.z;
        Qs[row * PAD + lc4 + 3] = v.w;
    }

    float m_[4], l_[4];
    unsigned long long accp[4][2];   // packed output accumulators
#pragma unroll
    for (int i = 0; i < 4; i++) {
        m_[i] = -INFINITY;
        l_[i] = 0.0f;
        accp[i][0] = 0ull;
        accp[i][1] = 0ull;
    }

    const float scale = 0.125f;

    for (int kt = 0; kt <= qt; kt++) {
        __syncthreads();

        const float* kb = qkv + ((size_t)(b * SEQ + kt * 64)) * (3 * DIM) + DIM + h * DH;
        const float* vb = kb + DIM;
#pragma unroll
        for (int rr = 0; rr < 4; rr++) {
            int row = rr * 16 + lr;
            float4 kv = *(const float4*)(kb + (size_t)row * (3 * DIM) + lc4);
            Kt[(lc4 + 0) * PAD + row] = kv.x;
            Kt[(lc4 + 1) * PAD + row] = kv.y;
            Kt[(lc4 + 2) * PAD + row] = kv.z;
            Kt[(lc4 + 3) * PAD + row] = kv.w;
            float4 vv = *(const float4*)(vb + (size_t)row * (3 * DIM) + lc4);
            Vs[row * PAD + lc4 + 0] = vv.x;
            Vs[row * PAD + lc4 + 1] = vv.y;
            Vs[row * PAD + lc4 + 2] = vv.z;
            Vs[row * PAD + lc4 + 3] = vv.w;
        }
        __syncthreads();

        // ---- scores: S = Q @ K^T (packed: 8 FFMA2 per d) ----
        unsigned long long s2[4][2];
#pragma unroll
        for (int i = 0; i < 4; i++) { s2[i][0] = 0ull; s2[i][1] = 0ull; }

#pragma unroll 8
        for (int d = 0; d < 64; d++) {
            unsigned long long kp0 = *(const unsigned long long*)&Kt[d * PAD + (tx << 2)];
            unsigned long long kp1 = *(const unsigned long long*)&Kt[d * PAD + (tx << 2) + 2];
#pragma unroll
            for (int i = 0; i < 4; i++) {
                unsigned long long qd;
                DUP2(qd, Qs[(ty * 4 + i) * PAD + d]);
                FMA2(s2[i][0], qd, kp0);
                FMA2(s2[i][1], qd, kp1);
            }
        }

        // unpack scores
        float s_[4][4];
#pragma unroll
        for (int i = 0; i < 4; i++) {
            UNPK2(s_[i][0], s_[i][1], s2[i][0]);
            UNPK2(s_[i][2], s_[i][3], s2[i][1]);
        }

        // ---- online softmax ----
#pragma unroll
        for (int i = 0; i < 4; i++) {
            float mx = -INFINITY;
#pragma unroll
            for (int j = 0; j < 4; j++) {
                float sv = s_[i][j] * scale;
                if (kt == qt && ((tx << 2) + j) > (ty * 4 + i)) sv = -INFINITY;
                s_[i][j] = sv;
                mx = fmaxf(mx, sv);
            }
#pragma unroll
            for (int off = 8; off > 0; off >>= 1)
                mx = fmaxf(mx, __shfl_xor_sync(0xffffffffu, mx, off));
            float mn  = fmaxf(m_[i], mx);
            float fac = expf(m_[i] - mn);
            float ps  = 0.0f;
#pragma unroll
            for (int j = 0; j < 4; j++) {
                float p = expf(s_[i][j] - mn);
                s_[i][j] = p;
                ps += p;
            }
#pragma unroll
            for (int off = 8; off > 0; off >>= 1)
                ps += __shfl_xor_sync(0xffffffffu, ps, off);
            m_[i] = mn;
            l_[i] = l_[i] * fac + ps;
            unsigned long long fd;
            DUP2(fd, fac);
            MUL2(accp[i][0], fd);
            MUL2(accp[i][1], fd);
        }

        // ---- stage P, then O += P @ V (packed) ----
#pragma unroll
        for (int i = 0; i < 4; i++)
#pragma unroll
            for (int j = 0; j < 4; j++)
                Ps[(ty * 4 + i) * PAD + (tx << 2) + j] = s_[i][j];
        __syncthreads();

#pragma unroll 4
        for (int k = 0; k < 64; k++) {
            unsigned long long vp0 = *(const unsigned long long*)&Vs[k * PAD + (tx << 2)];
            unsigned long long vp1 = *(const unsigned long long*)&Vs[k * PAD + (tx << 2) + 2];
#pragma unroll
            for (int i = 0; i < 4; i++) {
                unsigned long long pd;
                DUP2(pd, Ps[(ty * 4 + i) * PAD + k]);
                FMA2(accp[i][0], pd, vp0);
                FMA2(accp[i][1], pd, vp1);
            }
        }
    }

    // ---- write O (layout [B,T,H*DH]) ----
#pragma unroll
    for (int i = 0; i < 4; i++) {
        float inv = 1.0f / l_[i];
        float o0, o1, o2, o3;
        UNPK2(o0, o1, accp[i][0]);
        UNPK2(o2, o3, accp[i][1]);
        int grow = b * SEQ + qt * 64 + ty * 4 + i;
        float4 o = make_float4(o0 * inv, o1 * inv, o2 * inv, o3 * inv);
        *(float4*)&out[(size_t)grow * DIM + h * DH + (tx << 2)] = o;
    }
}

// ---------------------------------------------------------------------------
extern "C" void kernel_launch(void* const* d_in, const int* in_sizes, int n_in,
                              void* d_out, int out_size) {
    const float* x    = nullptr;
    const float* Wqkv = nullptr;
    const float* Wout = nullptr;
    for (int i = 0; i < n_in; i++) {
        if (in_sizes[i] == BATCH * SEQ * DIM)  x    = (const float*)d_in[i];
        else if (in_sizes[i] == 3 * DIM * DIM) Wqkv = (const float*)d_in[i];
        else if (in_sizes[i] == DIM * DIM)     Wout = (const float*)d_in[i];
    }
    float* out = (float*)d_out;

    float* qkv = nullptr;
    float* att = nullptr;
    cudaGetSymbolAddress((void**)&qkv, g_qkv);
    cudaGetSymbolAddress((void**)&att, g_att);

    const int M = BATCH * SEQ;  // 4096

    // 1) QKV projection: [4096,1024] @ [1024,3072]
    sgemm128<<<dim3(3 * DIM / 128, M / 128), 256>>>(x, Wqkv, qkv, M, 3 * DIM, DIM);

    // 2) RoPE (interleaved, -theta) on q and k
    rope_kernel<<<(BATCH * SEQ * 2 * NH * 16) / 256, 256>>>(qkv);

    // 3) Causal flash attention -> att [B,T,DIM]
    int smem = 4 * 64 * PAD * (int)sizeof(float);
    cudaFuncSetAttribute(attn_kernel, cudaFuncAttributeMaxDynamicSharedMemorySize, smem);
    attn_kernel<<<dim3(SEQ / 64, NH, BATCH), 256, smem>>>(qkv, att);

    // 4) Output projection: [4096,1024] @ [1024,1024]
    sgemm128<<<dim3(DIM / 128, M / 128), 256>>>(att, Wout, out, M, DIM, DIM);
}

// round 8
// speedup vs baseline: 1.2072x; 1.0793x over previous
#include <cuda_runtime.h>
#include <math.h>

#define BATCH 4
#define SEQ   1024
#define DIM   1024
#define NH    16
#define DH    64
#define PAD   68

// packed-f32x2 helpers
#define DUP2(d, s)      asm("mov.b64 %0, {%1, %1};" : "=l"(d) : "f"(s))
#define FMA2(a, x, y)   asm("fma.rn.f32x2 %0, %1, %2, %0;" : "+l"(a) : "l"(x), "l"(y))
#define MUL2(a, x)      asm("mul.rn.f32x2 %0, %1, %2;" : "=l"(a) : "l"(a), "l"(x))
#define UNPK2(lo, hi, v) asm("mov.b64 {%0, %1}, %2;" : "=f"(lo), "=f"(hi) : "l"(v))

__device__ float g_qkv[BATCH * SEQ * 3 * DIM];
__device__ float g_att[BATCH * SEQ * DIM];

// ---------------------------------------------------------------------------
// TF32 tensor-core GEMM with 3xTF32 compensation.
// C[M,N] = A[M,K] @ B[K,N], row-major. Block 128x128x32, 8 warps (2x4),
// warp tile 64x32, mma.sync.m16n8k8.tf32. a = a_hi + a_lo (tf32 split) done
// at the smem-fill stage; inner loop: D += ah*bh + ah*bl + al*bh.
// ---------------------------------------------------------------------------
#define SA_STRIDE 36    // 32 + 4: conflict-free A fragment loads
#define SB_STRIDE 136   // 128 + 8: conflict-free B fragment loads

__device__ __forceinline__ unsigned tf32_hi(float x) {
    unsigned h;
    asm("cvt.rna.tf32.f32 %0, %1;" : "=r"(h) : "f"(x));
    return h;
}

#define MMA_TF32(D, A, B)                                                    \
    asm("mma.sync.aligned.m16n8k8.row.col.f32.tf32.tf32.f32 "               \
        "{%0,%1,%2,%3}, {%4,%5,%6,%7}, {%8,%9}, {%0,%1,%2,%3};"             \
        : "+f"(D[0]), "+f"(D[1]), "+f"(D[2]), "+f"(D[3])                     \
        : "r"(A[0]), "r"(A[1]), "r"(A[2]), "r"(A[3]), "r"(B[0]), "r"(B[1]))

__global__ __launch_bounds__(256) void tf32gemm(const float* __restrict__ A,
                                                const float* __restrict__ B,
                                                float* __restrict__ C,
                                                int M, int N, int K) {
    extern __shared__ float sm[];
    float* sAh = sm;                          // [128][SA_STRIDE]
    float* sAl = sAh + 128 * SA_STRIDE;
    float* sBh = sAl + 128 * SA_STRIDE;       // [32][SB_STRIDE]
    float* sBl = sBh + 32 * SB_STRIDE;

    const int tid  = threadIdx.x;
    const int row0 = blockIdx.y * 128;
    const int col0 = blockIdx.x * 128;

    const int lane = tid & 31;
    const int wid  = tid >> 5;
    const int wm   = (wid >> 2) * 64;   // warp row base within block
    const int wn   = (wid & 3) * 32;    // warp col base within block
    const int g    = lane >> 2;         // group id (0..7)
    const int tg   = lane & 3;          // thread-in-group (0..3)

    float acc[4][4][4];
#pragma unroll
    for (int mt = 0; mt < 4; mt++)
#pragma unroll
        for (int nt = 0; nt < 4; nt++)
#pragma unroll
            for (int r = 0; r < 4; r++) acc[mt][nt][r] = 0.0f;

    for (int k0 = 0; k0 < K; k0 += 32) {
        // ---- fill smem with hi/lo tf32 split ----
#pragma unroll
        for (int v = 0; v < 4; v++) {             // A: 128x32
            int idx = tid + v * 256;              // 0..1023
            int r   = idx >> 3;                   // 0..127
            int c4  = (idx & 7) << 2;
            float4 a = *(const float4*)(A + (size_t)(row0 + r) * K + k0 + c4);
            float av[4] = {a.x, a.y, a.z, a.w};
#pragma unroll
            for (int e = 0; e < 4; e++) {
                unsigned h = tf32_hi(av[e]);
                float hf = __uint_as_float(h);
                unsigned l = tf32_hi(av[e] - hf);
                sAh[r * SA_STRIDE + c4 + e] = hf;
                sAl[r * SA_STRIDE + c4 + e] = __uint_as_float(l);
            }
        }
#pragma unroll
        for (int v = 0; v < 4; v++) {             // B: 32x128
            int idx = tid + v * 256;
            int r   = idx >> 5;                   // 0..31
            int c4  = (idx & 31) << 2;
            float4 b = *(const float4*)(B + (size_t)(k0 + r) * N + col0 + c4);
            float bv[4] = {b.x, b.y, b.z, b.w};
#pragma unroll
            for (int e = 0; e < 4; e++) {
                unsigned h = tf32_hi(bv[e]);
                float hf = __uint_as_float(h);
                unsigned l = tf32_hi(bv[e] - hf);
                sBh[r * SB_STRIDE + c4 + e] = hf;
                sBl[r * SB_STRIDE + c4 + e] = __uint_as_float(l);
            }
        }
        __syncthreads();

        // ---- 4 k-slices of 8 ----
#pragma unroll
        for (int ks = 0; ks < 4; ks++) {
            const int k = ks * 8;
            unsigned bh[4][2], bl[4][2];
#pragma unroll
            for (int nt = 0; nt < 4; nt++) {
                int col = wn + nt * 8 + g;
                bh[nt][0] = __float_as_uint(sBh[(k + tg) * SB_STRIDE + col]);
                bh[nt][1] = __float_as_uint(sBh[(k + 4 + tg) * SB_STRIDE + col]);
                bl[nt][0] = __float_as_uint(sBl[(k + tg) * SB_STRIDE + col]);
                bl[nt][1] = __float_as_uint(sBl[(k + 4 + tg) * SB_STRIDE + col]);
            }
#pragma unroll
            for (int mt = 0; mt < 4; mt++) {
                int r = wm + mt * 16 + g;
                unsigned ah[4], al[4];
                ah[0] = __float_as_uint(sAh[r * SA_STRIDE + k + tg]);
                ah[1] = __float_as_uint(sAh[(r + 8) * SA_STRIDE + k + tg]);
                ah[2] = __float_as_uint(sAh[r * SA_STRIDE + k + 4 + tg]);
                ah[3] = __float_as_uint(sAh[(r + 8) * SA_STRIDE + k + 4 + tg]);
                al[0] = __float_as_uint(sAl[r * SA_STRIDE + k + tg]);
                al[1] = __float_as_uint(sAl[(r + 8) * SA_STRIDE + k + tg]);
                al[2] = __float_as_uint(sAl[r * SA_STRIDE + k + 4 + tg]);
                al[3] = __float_as_uint(sAl[(r + 8) * SA_STRIDE + k + 4 + tg]);
#pragma unroll
                for (int nt = 0; nt < 4; nt++) {
                    MMA_TF32(acc[mt][nt], ah, bh[nt]);
                    MMA_TF32(acc[mt][nt], ah, bl[nt]);
                    MMA_TF32(acc[mt][nt], al, bh[nt]);
                }
            }
        }
        __syncthreads();
    }

    // ---- epilogue ----
#pragma unroll
    for (int mt = 0; mt < 4; mt++)
#pragma unroll
        for (int nt = 0; nt < 4; nt++) {
            int r = row0 + wm + mt * 16 + g;
            int c = col0 + wn + nt * 8 + tg * 2;
            *(float2*)&C[(size_t)r * N + c]       = make_float2(acc[mt][nt][0], acc[mt][nt][1]);
            *(float2*)&C[(size_t)(r + 8) * N + c] = make_float2(acc[mt][nt][2], acc[mt][nt][3]);
        }
}

#define GEMM_SMEM ((2 * 128 * SA_STRIDE + 2 * 32 * SB_STRIDE) * (int)sizeof(float))

// ---------------------------------------------------------------------------
// RoPE — interleaved pairs (2i, 2i+1), rotation by -theta (verified R6).
// ---------------------------------------------------------------------------
__global__ void rope_kernel(float* __restrict__ qkv) {
    int idx = blockIdx.x * blockDim.x + threadIdx.x;
    int i = idx & 15;
    int h = (idx >> 4) & 15;
    int s = (idx >> 8) & 1;
    int t = (idx >> 9) & 1023;
    int b = idx >> 19;

    float inv_freq = powf(10000.0f, -(float)(2 * i) / 32.0f);
    float ang = (float)t * inv_freq;
    float c, sn;
    sincosf(ang, &c, &sn);

    size_t base = ((size_t)(b * SEQ + t)) * (3 * DIM) + s * DIM + h * DH + 2 * i;
    float v0 = qkv[base], v1 = qkv[base + 1];
    qkv[base]     = v0 * c + v1 * sn;
    qkv[base + 1] = v1 * c - v0 * sn;
}

// ---------------------------------------------------------------------------
// Flash attention (causal), fp32, f32x2-packed inner products (R7, passing).
// ---------------------------------------------------------------------------
__global__ __launch_bounds__(256) void attn_kernel(const float* __restrict__ qkv,
                                                   float* __restrict__ out) {
    extern __shared__ float sm[];
    float* Qs = sm;
    float* Kt = Qs + 64 * PAD;
    float* Vs = Kt + 64 * PAD;
    float* Ps = Vs + 64 * PAD;

    const int qt = blockIdx.x;
    const int h  = blockIdx.y;
    const int b  = blockIdx.z;
    const int tid = threadIdx.x;
    const int ty = tid >> 4, tx = tid & 15;
    const int lr = tid >> 4, lc4 = (tid & 15) << 2;

    const float* qb = qkv + ((size_t)(b * SEQ + qt * 64)) * (3 * DIM) + h * DH;
#pragma unroll
    for (int rr = 0; rr < 4; rr++) {
        int row = rr * 16 + lr;
        float4 v = *(const float4*)(qb + (size_t)row * (3 * DIM) + lc4);
        Qs[row * PAD + lc4 + 0] = v.x;
        Qs[row * PAD + lc4 + 1] = v.y;
        Qs[row * PAD + lc4 + 2] = v.z;
        Qs[row * PAD + lc4 + 3] = v.w;
    }

    float m_[4], l_[4];
    unsigned long long accp[4][2];
#pragma unroll
    for (int i = 0; i < 4; i++) {
        m_[i] = -INFINITY;
        l_[i] = 0.0f;
        accp[i][0] = 0ull;
        accp[i][1] = 0ull;
    }

    const float scale = 0.125f;

    for (int kt = 0; kt <= qt; kt++) {
        __syncthreads();

        const float* kb = qkv + ((size_t)(b * SEQ + kt * 64)) * (3 * DIM) + DIM + h * DH;
        const float* vb = kb + DIM;
#pragma unroll
        for (int rr = 0; rr < 4; rr++) {
            int row = rr * 16 + lr;
            float4 kv = *(const float4*)(kb + (size_t)row * (3 * DIM) + lc4);
            Kt[(lc4 + 0) * PAD + row] = kv.x;
            Kt[(lc4 + 1) * PAD + row] = kv.y;
            Kt[(lc4 + 2) * PAD + row] = kv.z;
            Kt[(lc4 + 3) * PAD + row] = kv.w;
            float4 vv = *(const float4*)(vb + (size_t)row * (3 * DIM) + lc4);
            Vs[row * PAD + lc4 + 0] = vv.x;
            Vs[row * PAD + lc4 + 1] = vv.y;
            Vs[row * PAD + lc4 + 2] = vv.z;
            Vs[row * PAD + lc4 + 3] = vv.w;
        }
        __syncthreads();

        unsigned long long s2[4][2];
#pragma unroll
        for (int i = 0; i < 4; i++) { s2[i][0] = 0ull; s2[i][1] = 0ull; }

#pragma unroll 8
        for (int d = 0; d < 64; d++) {
            unsigned long long kp0 = *(const unsigned long long*)&Kt[d * PAD + (tx << 2)];
            unsigned long long kp1 = *(const unsigned long long*)&Kt[d * PAD + (tx << 2) + 2];
#pragma unroll
            for (int i = 0; i < 4; i++) {
                unsigned long long qd;
                DUP2(qd, Qs[(ty * 4 + i) * PAD + d]);
                FMA2(s2[i][0], qd, kp0);
                FMA2(s2[i][1], qd, kp1);
            }
        }

        float s_[4][4];
#pragma unroll
        for (int i = 0; i < 4; i++) {
            UNPK2(s_[i][0], s_[i][1], s2[i][0]);
            UNPK2(s_[i][2], s_[i][3], s2[i][1]);
        }

#pragma unroll
        for (int i = 0; i < 4; i++) {
            float mx = -INFINITY;
#pragma unroll
            for (int j = 0; j < 4; j++) {
                float sv = s_[i][j] * scale;
                if (kt == qt && ((tx << 2) + j) > (ty * 4 + i)) sv = -INFINITY;
                s_[i][j] = sv;
                mx = fmaxf(mx, sv);
            }
#pragma unroll
            for (int off = 8; off > 0; off >>= 1)
                mx = fmaxf(mx, __shfl_xor_sync(0xffffffffu, mx, off));
            float mn  = fmaxf(m_[i], mx);
            float fac = expf(m_[i] - mn);
            float ps  = 0.0f;
#pragma unroll
            for (int j = 0; j < 4; j++) {
                float p = expf(s_[i][j] - mn);
                s_[i][j] = p;
                ps += p;
            }
#pragma unroll
            for (int off = 8; off > 0; off >>= 1)
                ps += __shfl_xor_sync(0xffffffffu, ps, off);
            m_[i] = mn;
            l_[i] = l_[i] * fac + ps;
            unsigned long long fd;
            DUP2(fd, fac);
            MUL2(accp[i][0], fd);
            MUL2(accp[i][1], fd);
        }

#pragma unroll
        for (int i = 0; i < 4; i++)
#pragma unroll
            for (int j = 0; j < 4; j++)
                Ps[(ty * 4 + i) * PAD + (tx << 2) + j] = s_[i][j];
        __syncthreads();

#pragma unroll 4
        for (int k = 0; k < 64; k++) {
            unsigned long long vp0 = *(const unsigned long long*)&Vs[k * PAD + (tx << 2)];
            unsigned long long vp1 = *(const unsigned long long*)&Vs[k * PAD + (tx << 2) + 2];
#pragma unroll
            for (int i = 0; i < 4; i++) {
                unsigned long long pd;
                DUP2(pd, Ps[(ty * 4 + i) * PAD + k]);
                FMA2(accp[i][0], pd, vp0);
                FMA2(accp[i][1], pd, vp1);
            }
        }
    }

#pragma unroll
    for (int i = 0; i < 4; i++) {
        float inv = 1.0f / l_[i];
        float o0, o1, o2, o3;
        UNPK2(o0, o1, accp[i][0]);
        UNPK2(o2, o3, accp[i][1]);
        int grow = b * SEQ + qt * 64 + ty * 4 + i;
        float4 o = make_float4(o0 * inv, o1 * inv, o2 * inv, o3 * inv);
        *(float4*)&out[(size_t)grow * DIM + h * DH + (tx << 2)] = o;
    }
}

// ---------------------------------------------------------------------------
extern "C" void kernel_launch(void* const* d_in, const int* in_sizes, int n_in,
                              void* d_out, int out_size) {
    const float* x    = nullptr;
    const float* Wqkv = nullptr;
    const float* Wout = nullptr;
    for (int i = 0; i < n_in; i++) {
        if (in_sizes[i] == BATCH * SEQ * DIM)  x    = (const float*)d_in[i];
        else if (in_sizes[i] == 3 * DIM * DIM) Wqkv = (const float*)d_in[i];
        else if (in_sizes[i] == DIM * DIM)     Wout = (const float*)d_in[i];
    }
    float* out = (float*)d_out;

    float* qkv = nullptr;
    float* att = nullptr;
    cudaGetSymbolAddress((void**)&qkv, g_qkv);
    cudaGetSymbolAddress((void**)&att, g_att);

    const int M = BATCH * SEQ;  // 4096

    cudaFuncSetAttribute(tf32gemm, cudaFuncAttributeMaxDynamicSharedMemorySize, GEMM_SMEM);

    // 1) QKV projection: [4096,1024] @ [1024,3072]
    tf32gemm<<<dim3(3 * DIM / 128, M / 128), 256, GEMM_SMEM>>>(x, Wqkv, qkv, M, 3 * DIM, DIM);

    // 2) RoPE (interleaved, -theta)
    rope_kernel<<<(BATCH * SEQ * 2 * NH * 16) / 256, 256>>>(qkv);

    // 3) Causal flash attention -> att
    int smem = 4 * 64 * PAD * (int)sizeof(float);
    cudaFuncSetAttribute(attn_kernel, cudaFuncAttributeMaxDynamicSharedMemorySize, smem);
    attn_kernel<<<dim3(SEQ / 64, NH, BATCH), 256, smem>>>(qkv, att);

    // 4) Output projection: [4096,1024] @ [1024,1024]
    tf32gemm<<<dim3(DIM / 128, M / 128), 256, GEMM_SMEM>>>(att, Wout, out, M, DIM, DIM);
}